// round 4
// baseline (speedup 1.0000x reference)
#include <cuda_runtime.h>
#include <cuda_fp8.h>
#include <stdint.h>

#define N_SAMPLES 32768
#define N_ATOMS   2048
#define ATOM_SIZE 1024
#define K_SPARSE  64
#define BATCH     4
#define PADN      33824   // 512 pad + 32768 + 512 pad + 32 slack (zeroed)
#define CAP       65536

// k2 tiling (int8 path)
#define MT   128                 // CTA time-tile
#define NT   128                 // CTA atom-tile
#define KCB  128                 // K bytes per chunk (128 int8)
#define NCHUNK 8                 // 1024/128
#define A_STRIDE 1168            // window copy stride (16B-aligned, 16B bank phase)
#define A_BYTES (16 * A_STRIDE)  // 18688: 16 shift copies, persistent (all K)
#define B_BYTES (NT * KCB)       // 16384 per stage
#define SMEM_DYN (A_BYTES + 2 * B_BYTES)   // 51456

// ---------------- device scratch (static, allocation-free) ----------------
__device__ __align__(16) signed char g_shift[16 * BATCH * PADN];  // 16 shifted int8 copies
__device__ float       g_origpad_f[BATCH * PADN];
__device__ __align__(16) signed char g_atoms_i8[N_ATOMS * ATOM_SIZE];
__device__ unsigned    g_cnt[BATCH];
__device__ unsigned    g_maxnorm_u;
__device__ float       g_origss[BATCH];
__device__ float       g_thresh[BATCH];
__device__ float       g_scale_o[BATCH];   // orig quant scale
__device__ float       g_inv_sc[BATCH];    // 1/(scale_o*127)
__device__ unsigned    g_cand_idx  [BATCH * CAP];
__device__ float       g_cand_score[BATCH * CAP];
__device__ float       g_sel_val[BATCH * K_SPARSE];
__device__ int         g_sel_at [BATCH * K_SPARSE];
__device__ int         g_sel_tm [BATCH * K_SPARSE];

// ---------------- PTX helpers ----------------
#define LDM4(R0,R1,R2,R3,ADDR) \
    asm volatile("ldmatrix.sync.aligned.m8n8.x4.shared.b16 {%0,%1,%2,%3},[%4];" \
                 : "=r"(R0), "=r"(R1), "=r"(R2), "=r"(R3) : "r"(ADDR))

#define IMMA16832(D, A, B0, B1) \
    asm volatile("mma.sync.aligned.m16n8k32.row.col.s32.s8.s8.s32 " \
                 "{%0,%1,%2,%3},{%4,%5,%6,%7},{%8,%9},{%0,%1,%2,%3};" \
                 : "+r"(D[0]), "+r"(D[1]), "+r"(D[2]), "+r"(D[3]) \
                 : "r"(A[0]), "r"(A[1]), "r"(A[2]), "r"(A[3]), "r"(B0), "r"(B1))

__device__ __forceinline__ void cp16_ca(unsigned dst, const void* src) {
    asm volatile("cp.async.ca.shared.global [%0], [%1], 16;" :: "r"(dst), "l"(src));
}
__device__ __forceinline__ void cp16_cg(unsigned dst, const void* src) {
    asm volatile("cp.async.cg.shared.global [%0], [%1], 16;" :: "r"(dst), "l"(src));
}
#define CP_COMMIT() asm volatile("cp.async.commit_group;")

// ---------------- K_init ----------------
__global__ void k_init() {
    if (threadIdx.x < BATCH) g_cnt[threadIdx.x] = 0u;
    if (threadIdx.x == 4)    g_maxnorm_u = 0u;
}

// ---------------- K0: stats ----------------
__global__ void k0_stats(const float* __restrict__ orig, const float* __restrict__ atoms) {
    __shared__ float red[256];
    int tid = threadIdx.x, bid = blockIdx.x;
    float s = 0.f;
    if (bid < N_ATOMS) {
        const float* a = atoms + (size_t)bid * ATOM_SIZE;
        for (int i = tid; i < ATOM_SIZE; i += 256) { float v = a[i]; s += v * v; }
    } else {
        int b = bid - N_ATOMS;
        const float* o = orig + (size_t)b * N_SAMPLES;
        for (int i = tid; i < N_SAMPLES; i += 256) { float v = o[i]; s += v * v; }
    }
    red[tid] = s; __syncthreads();
    for (int st = 128; st; st >>= 1) { if (tid < st) red[tid] += red[tid + st]; __syncthreads(); }
    if (tid == 0) {
        if (bid < N_ATOMS) atomicMax(&g_maxnorm_u, __float_as_uint(red[0]));
        else               g_origss[bid - N_ATOMS] = red[0];
    }
}

__global__ void k0b_thresh() {
    int b = threadIdx.x;
    if (b < BATCH) {
        float ms   = g_origss[b] / (float)N_SAMPLES;     // mean square
        float rms  = sqrtf(fmaxf(ms, 1e-20f));
        float sig2 = __uint_as_float(g_maxnorm_u) * ms;
        g_thresh[b]  = 3.5f * sqrtf(sig2);
        float sc     = 127.f / (6.f * rms);              // clip beyond 6*rms (prob ~0)
        g_scale_o[b] = sc;
        g_inv_sc[b]  = 1.f / (sc * 127.f);
    }
}

// ---------------- K1: int8 quantize + 16 shifted padded copies ----------
__global__ void k1_convert(const float* __restrict__ orig, const float* __restrict__ atoms) {
    int i = blockIdx.x * 256 + threadIdx.x;
    if (i < N_ATOMS * ATOM_SIZE) {
        int q = __float2int_rn(atoms[i] * 127.f);
        g_atoms_i8[i] = (signed char)max(-127, min(127, q));
    }
    if (i < BATCH * PADN) {
        int b = i / PADN, p = i - b * PADN;
        int src = p - 512;
        g_origpad_f[i] = (src >= 0 && src < N_SAMPLES) ? orig[b * N_SAMPLES + src] : 0.f;
    }
    // 16 copies: g_shift[(s*BATCH+b)*PADN + j] = quant(origpad(b, j+s))
    if (i < 16 * BATCH * PADN) {
        int s = i / (BATCH * PADN);
        int r = i - s * (BATCH * PADN);
        int b = r / PADN, j = r - b * PADN;
        int src = j + s - 512;
        float v = (src >= 0 && src < N_SAMPLES) ? orig[b * N_SAMPLES + src] : 0.f;
        int q = __float2int_rn(v * g_scale_o[b]);
        g_shift[i] = (signed char)max(-127, min(127, q));
    }
}

// ---------------- K2: int8 mma.sync scoring (m16n8k32) ----------------
// CTA 128 times x 128 atoms, K=1024 in 8 chunks of 128 bytes.
// A: persistent 16-shift Hankel window in smem (18.3KB covers all K).
// B: atoms, double-buffered cp.async.cg, XOR-16 swizzle. 8 warps (4M x 2N), warp 32x64.
extern __shared__ __align__(16) unsigned char sm_dyn[];

__global__ void __launch_bounds__(256, 1) k2_score() {
    const int b  = blockIdx.z;
    const int t0 = blockIdx.x * MT;
    const int a0 = blockIdx.y * NT;
    const int tid  = threadIdx.x;
    const int lane = tid & 31;
    const int wid  = tid >> 5;
    const int mw = (wid >> 1) * 32;   // warp M offset (time), 4 warps
    const int nw = (wid & 1) * 64;    // warp N offset (atoms), 2 warps

    const unsigned Abase = (unsigned)__cvta_generic_to_shared(sm_dyn);
    const unsigned Bbase = Abase + (unsigned)A_BYTES;

    // ---- fill persistent A window: 16 copies x 1168B (73 x 16B each) ----
    for (int u = tid; u < 16 * 73; u += 256) {
        int s = u / 73, c = u - s * 73;
        const char* src = (const char*)g_shift + (size_t)(s * BATCH + b) * PADN + t0 + c * 16;
        cp16_ca(Abase + (unsigned)(s * A_STRIDE + c * 16), src);
    }
    CP_COMMIT();

    // ---- B chunk fill (128 atoms x 8 x 16B, XOR swizzle) ----
    auto cpB = [&](int kb) {
        unsigned dstb = Bbase + (unsigned)((kb & 1) * B_BYTES);
        const char* src0 = (const char*)g_atoms_i8 + (size_t)a0 * ATOM_SIZE + (size_t)kb * KCB;
        #pragma unroll
        for (int i = tid; i < 1024; i += 256) {
            int n = i >> 3, c = i & 7;
            unsigned dst = dstb + (unsigned)((n >> 3) * 1024 + (n & 7) * 128 + ((c ^ (n & 7)) * 16));
            cp16_cg(dst, src0 + (size_t)n * ATOM_SIZE + c * 16);
        }
    };

    cpB(0); CP_COMMIT();

    // lane-fixed addresses
    // A: row r = base + s, s = lane&15 (shift copy), base = mw + mt*16 (16-aligned)
    unsigned aaddr[2];
    #pragma unroll
    for (int mt = 0; mt < 2; mt++)
        aaddr[mt] = Abase + (unsigned)((lane & 15) * A_STRIDE + mw + mt * 16 + ((lane >> 4) & 1) * 16);
    // B: atom rows via npL, k-half via lane>>3
    const int npL = 8 * ((lane >> 4) & 1) + (lane & 7);
    const unsigned swz   = (unsigned)((lane & 7) * 16);
    const unsigned khalf = (unsigned)(16 * ((lane >> 3) & 1));
    unsigned bn[4];
    #pragma unroll
    for (int j = 0; j < 4; j++) {
        int atom = nw + j * 16 + npL;
        bn[j] = (unsigned)((atom >> 3) * 1024 + (atom & 7) * 128);
    }

    int acc[2][8][4];
    #pragma unroll
    for (int mt = 0; mt < 2; mt++)
        #pragma unroll
        for (int nt = 0; nt < 8; nt++)
            #pragma unroll
            for (int c = 0; c < 4; c++) acc[mt][nt][c] = 0;

    for (int kb = 0; kb < NCHUNK; kb++) {
        if (kb + 1 < NCHUNK) {
            cpB(kb + 1);
            CP_COMMIT();
            asm volatile("cp.async.wait_group 1;");
        } else {
            asm volatile("cp.async.wait_group 0;");
        }
        __syncthreads();
        const unsigned bufo = (unsigned)((kb & 1) * B_BYTES);
        #pragma unroll
        for (int ks = 0; ks < 4; ks++) {                 // 32 bytes of K per step
            const unsigned kbyte = (unsigned)(kb * KCB + ks * 32);
            uint32_t afr[2][4];
            LDM4(afr[0][0], afr[0][1], afr[0][2], afr[0][3], aaddr[0] + kbyte);
            LDM4(afr[1][0], afr[1][1], afr[1][2], afr[1][3], aaddr[1] + kbyte);
            uint32_t bfr[8][2];
            const unsigned koff = ((unsigned)(ks * 32) + khalf) ^ swz;
            #pragma unroll
            for (int j = 0; j < 4; j++)
                LDM4(bfr[2*j][0], bfr[2*j][1], bfr[2*j+1][0], bfr[2*j+1][1],
                     Bbase + bufo + bn[j] + koff);
            #pragma unroll
            for (int mt = 0; mt < 2; mt++)
                #pragma unroll
                for (int nt = 0; nt < 8; nt++)
                    IMMA16832(acc[mt][nt], afr[mt], bfr[nt][0], bfr[nt][1]);
        }
        __syncthreads();
    }

    // ---- epilogue: descale + threshold gate -> candidate append ----
    const float T   = g_thresh[b];
    const float inv = g_inv_sc[b];
    const int g = lane >> 2, t4 = lane & 3;
    #pragma unroll
    for (int mt = 0; mt < 2; mt++)
        #pragma unroll
        for (int nt = 0; nt < 8; nt++)
            #pragma unroll
            for (int ci = 0; ci < 4; ci++) {
                float v = inv * (float)acc[mt][nt][ci];
                if (v > T) {
                    int time = t0 + mw + mt * 16 + g + 8 * (ci >> 1);
                    int atom = a0 + nw + nt * 8 + 2 * t4 + (ci & 1);
                    unsigned pos = atomicAdd(&g_cnt[b], 1u);
                    if (pos < CAP) g_cand_idx[b * CAP + pos] = ((unsigned)atom << 16) | (unsigned)time;
                }
            }
}

// ---------------- K3: exact fp32 re-score ----------------
__global__ void k3_rescore(const float* __restrict__ atoms) {
    int b = blockIdx.y;
    int warp = blockIdx.x * 8 + (threadIdx.x >> 5);
    int lane = threadIdx.x & 31;
    unsigned n = min(g_cnt[b], (unsigned)CAP);
    for (unsigned i = warp; i < n; i += 512) {
        unsigned pk = g_cand_idx[b * CAP + i];
        int atom = (int)(pk >> 16), t = (int)(pk & 0xFFFF);
        const float* op = g_origpad_f + (size_t)b * PADN + t;
        const float* ap = atoms + (size_t)atom * ATOM_SIZE;
        float s = 0.f;
        for (int k = lane; k < ATOM_SIZE; k += 32) s += op[k] * ap[k];
        #pragma unroll
        for (int o = 16; o; o >>= 1) s += __shfl_xor_sync(0xFFFFFFFFu, s, o);
        if (lane == 0) g_cand_score[b * CAP + i] = s;
    }
}

// ---------------- K4: exact top-64 (64 argmax rounds) ----------------
__global__ void k4_select() {
    int b = blockIdx.x;
    int tid = threadIdx.x;
    unsigned n = min(g_cnt[b], (unsigned)CAP);
    __shared__ float sv[256];
    __shared__ int   si[256];
    float* sc = g_cand_score + (size_t)b * CAP;
    for (int r = 0; r < K_SPARSE; r++) {
        float bv = -1e30f; int bi = -1;
        for (unsigned i = tid; i < n; i += 256) {
            float v = sc[i];
            if (v > bv) { bv = v; bi = (int)i; }
        }
        sv[tid] = bv; si[tid] = bi; __syncthreads();
        for (int st = 128; st; st >>= 1) {
            if (tid < st && sv[tid + st] > sv[tid]) { sv[tid] = sv[tid + st]; si[tid] = si[tid + st]; }
            __syncthreads();
        }
        if (tid == 0) {
            int i = si[0];
            unsigned pk = (i >= 0) ? g_cand_idx[b * CAP + i] : 0u;
            g_sel_val[b * K_SPARSE + r] = (i >= 0) ? sv[0] : 0.f;
            g_sel_at [b * K_SPARSE + r] = (int)(pk >> 16);
            g_sel_tm [b * K_SPARSE + r] = (int)(pk & 0xFFFF);
            if (i >= 0) sc[i] = -1e30f;
        }
        __syncthreads();
    }
}

// ---------------- K5: gather reconstruction ----------------
__global__ void k5_recon(const float* __restrict__ atoms, float* __restrict__ out) {
    int b = blockIdx.y;
    int t = blockIdx.x * 256 + threadIdx.x;
    __shared__ float v[K_SPARSE];
    __shared__ int   at[K_SPARSE], tmx[K_SPARSE];
    if (threadIdx.x < K_SPARSE) {
        v  [threadIdx.x] = g_sel_val[b * K_SPARSE + threadIdx.x];
        at [threadIdx.x] = g_sel_at [b * K_SPARSE + threadIdx.x];
        tmx[threadIdx.x] = g_sel_tm [b * K_SPARSE + threadIdx.x];
    }
    __syncthreads();
    float s = 0.f;
    for (int e = 0; e < K_SPARSE; e++) {
        int d = t - tmx[e];
        if ((unsigned)d < (unsigned)ATOM_SIZE) s += atoms[(size_t)at[e] * ATOM_SIZE + d] * v[e];
    }
    out[(size_t)b * N_SAMPLES + t] = s;
}

// ---------------- launch ----------------
extern "C" void kernel_launch(void* const* d_in, const int* in_sizes, int n_in,
                              void* d_out, int out_size) {
    const float* orig  = (const float*)d_in[0];   // [4,1,32768]
    const float* atoms = (const float*)d_in[1];   // [2048,1024]
    float* out = (float*)d_out;                   // [4,1,32768]

    cudaFuncSetAttribute(k2_score, cudaFuncAttributeMaxDynamicSharedMemorySize, SMEM_DYN);

    k_init<<<1, 32>>>();
    k0_stats<<<N_ATOMS + BATCH, 256>>>(orig, atoms);
    k0b_thresh<<<1, 32>>>();
    k1_convert<<<(16 * BATCH * PADN) / 256, 256>>>(orig, atoms);  // 8456 blocks, covers all arrays
    k2_score<<<dim3(N_SAMPLES / MT, N_ATOMS / NT, BATCH), 256, SMEM_DYN>>>();
    k3_rescore<<<dim3(64, BATCH), 256>>>(atoms);
    k4_select<<<BATCH, 256>>>();
    k5_recon<<<dim3(N_SAMPLES / 256, BATCH), 256>>>(atoms, out);
}

// round 7
// speedup vs baseline: 2.7954x; 2.7954x over previous
#include <cuda_runtime.h>
#include <cuda_bf16.h>
#include <stdint.h>

#define N_SAMPLES 32768
#define N_ATOMS   2048
#define ATOM_SIZE 1024
#define K_SPARSE  64
#define BATCH     4
#define PADN      33824   // 512 pad + 32768 + 512 pad + 32 slack (zeroed)
#define CAP       65536

// k2 tiling (bf16, m16n8k16)
#define MT   256                  // CTA time-tile (4 M-warps x 64)
#define NT   64                   // CTA atom-tile (2 N-warps x 32)
#define KC   64                   // K elems per chunk (128B bf16 row)
#define NCHUNK 16                 // 1024/64
#define ASTRIDE 2608              // bytes per shift copy: 163*16, 163%8==3 -> conflict-free
#define A_BYTES (8 * ASTRIDE)     // 20864, persistent (covers all K)
#define BSTAGE  (NT * 128)        // 8192 B per stage
#define NBSTAGE 3
#define SMEM_DYN (A_BYTES + NBSTAGE * BSTAGE + 128)

// ---------------- device scratch (static, allocation-free) ----------------
__device__ __align__(16) __nv_bfloat16 g_shift[8 * BATCH * PADN];  // 8 shifted padded copies
__device__ float         g_origpad_f[BATCH * PADN];
__device__ __align__(16) __nv_bfloat16 g_atoms_bf[N_ATOMS * ATOM_SIZE];
__device__ unsigned      g_cnt[BATCH];
__device__ unsigned      g_maxnorm_u;
__device__ float         g_origss[BATCH];
__device__ float         g_thresh[BATCH];
__device__ unsigned      g_cand_idx  [BATCH * CAP];
__device__ float         g_cand_score[BATCH * CAP];
__device__ float         g_sel_val[BATCH * K_SPARSE];
__device__ int           g_sel_at [BATCH * K_SPARSE];
__device__ int           g_sel_tm [BATCH * K_SPARSE];

// ---------------- PTX helpers ----------------
#define LDM4(R0,R1,R2,R3,ADDR) \
    asm volatile("ldmatrix.sync.aligned.m8n8.x4.shared.b16 {%0,%1,%2,%3},[%4];" \
                 : "=r"(R0), "=r"(R1), "=r"(R2), "=r"(R3) : "r"(ADDR))

#define MMA16816(D, A, B0, B1) \
    asm volatile("mma.sync.aligned.m16n8k16.row.col.f32.bf16.bf16.f32 " \
                 "{%0,%1,%2,%3},{%4,%5,%6,%7},{%8,%9},{%0,%1,%2,%3};" \
                 : "+f"(D[0]), "+f"(D[1]), "+f"(D[2]), "+f"(D[3]) \
                 : "r"(A[0]), "r"(A[1]), "r"(A[2]), "r"(A[3]), "r"(B0), "r"(B1))

__device__ __forceinline__ void cp16_ca(unsigned dst, const void* src) {
    asm volatile("cp.async.ca.shared.global [%0], [%1], 16;" :: "r"(dst), "l"(src));
}
__device__ __forceinline__ void cp16_cg(unsigned dst, const void* src) {
    asm volatile("cp.async.cg.shared.global [%0], [%1], 16;" :: "r"(dst), "l"(src));
}
#define CP_COMMIT() asm volatile("cp.async.commit_group;")

// ---------------- K_init ----------------
__global__ void k_init() {
    if (threadIdx.x < BATCH) g_cnt[threadIdx.x] = 0u;
    if (threadIdx.x == 4)    g_maxnorm_u = 0u;
}

// ---------------- K0: stats ----------------
__global__ void k0_stats(const float* __restrict__ orig, const float* __restrict__ atoms) {
    __shared__ float red[256];
    int tid = threadIdx.x, bid = blockIdx.x;
    float s = 0.f;
    if (bid < N_ATOMS) {
        const float* a = atoms + (size_t)bid * ATOM_SIZE;
        for (int i = tid; i < ATOM_SIZE; i += 256) { float v = a[i]; s += v * v; }
    } else {
        int b = bid - N_ATOMS;
        const float* o = orig + (size_t)b * N_SAMPLES;
        for (int i = tid; i < N_SAMPLES; i += 256) { float v = o[i]; s += v * v; }
    }
    red[tid] = s; __syncthreads();
    for (int st = 128; st; st >>= 1) { if (tid < st) red[tid] += red[tid + st]; __syncthreads(); }
    if (tid == 0) {
        if (bid < N_ATOMS) atomicMax(&g_maxnorm_u, __float_as_uint(red[0]));
        else               g_origss[bid - N_ATOMS] = red[0];
    }
}

__global__ void k0b_thresh() {
    int b = threadIdx.x;
    if (b < BATCH) {
        float sigma2 = __uint_as_float(g_maxnorm_u) * (g_origss[b] / (float)N_SAMPLES);
        g_thresh[b] = 3.5f * sqrtf(sigma2);
    }
}

// ---------------- K1: bf16 convert + 8 shifted padded copies ----------
__global__ void k1_convert(const float* __restrict__ orig, const float* __restrict__ atoms) {
    int i = blockIdx.x * 256 + threadIdx.x;
    if (i < N_ATOMS * ATOM_SIZE) g_atoms_bf[i] = __float2bfloat16(atoms[i]);
    if (i < BATCH * PADN) {
        int b = i / PADN, p = i - b * PADN;
        int src = p - 512;
        g_origpad_f[i] = (src >= 0 && src < N_SAMPLES) ? orig[b * N_SAMPLES + src] : 0.f;
    }
    if (i < 8 * BATCH * PADN) {
        int s = i / (BATCH * PADN);
        int r = i - s * (BATCH * PADN);
        int b = r / PADN, j = r - b * PADN;
        int src = j + s - 512;
        float v = (src >= 0 && src < N_SAMPLES) ? orig[b * N_SAMPLES + src] : 0.f;
        g_shift[i] = __float2bfloat16(v);
    }
}

// ---------------- K2: bf16 mma.sync scoring, persistent Hankel A ----------
// CTA 256 times x 64 atoms, K=1024 in 16 chunks of 64.
// A: persistent 8-shift window (20.4KB, conflict-free stride), filled once.
// B: 3-stage cp.async.cg ring, fill-ahead 2, one __syncthreads per chunk.
// 8 warps: 4 in M (64 each) x 2 in N (32 each). Per k-step: 6 LDSM, 16 MMA.
extern __shared__ __align__(16) unsigned char sm_dyn[];

__global__ void __launch_bounds__(256) k2_score() {
    const int b  = blockIdx.z;
    const int t0 = blockIdx.x * MT;
    const int a0 = blockIdx.y * NT;
    const int tid  = threadIdx.x;
    const int lane = tid & 31;
    const int wid  = tid >> 5;
    const int mw = (wid >> 1) * 64;   // 4 M-warps
    const int nw = (wid & 1) * 32;    // 2 N-warps

    const unsigned Abase = ((unsigned)__cvta_generic_to_shared(sm_dyn) + 127u) & ~127u;
    const unsigned Bbase = Abase + (unsigned)A_BYTES;

    // ---- persistent A fill: 8 copies x 163 x 16B ----
    for (int u = tid; u < 8 * 163; u += 256) {
        int s = u & 7, c = u >> 3;
        const char* src = (const char*)g_shift
            + 2u * ((uint32_t)(s * BATCH + b) * PADN + (uint32_t)(t0 + c * 8));
        cp16_ca(Abase + (unsigned)(s * ASTRIDE + c * 16), src);
    }
    // ---- B chunk fill: 64 atoms x 8 x 16B, XOR-16 swizzle ----
    auto cpB = [&](int kb) {
        unsigned dstb = Bbase + (unsigned)((kb % NBSTAGE) * BSTAGE);
        const char* src0 = (const char*)g_atoms_bf + 2u * ((uint32_t)a0 * ATOM_SIZE + (uint32_t)kb * KC);
        #pragma unroll
        for (int i = tid; i < 512; i += 256) {
            int n = i >> 3, c = i & 7;
            unsigned dst = dstb + (unsigned)(n * 128 + ((c ^ (n & 7)) * 16));
            cp16_cg(dst, src0 + (size_t)n * (ATOM_SIZE * 2) + c * 16);
        }
    };

    cpB(0); CP_COMMIT();          // g0 = A + B0
    cpB(1); CP_COMMIT();          // g1 = B1

    // lane-fixed A addresses (row = mw + mt*16 + (lane&7) + 8*((lane>>3)&1); copy = lane&7)
    unsigned aaddr[4];
    #pragma unroll
    for (int mt = 0; mt < 4; mt++)
        aaddr[mt] = Abase + (unsigned)((lane & 7) * ASTRIDE
                  + 2 * (mw + mt * 16 + 8 * ((lane >> 3) & 1)) + 16 * ((lane >> 4) & 1));
    // B lane addressing (identical to validated R1 formulas)
    const int npL = 8 * ((lane >> 4) & 1) + (lane & 7);
    const unsigned swz   = (unsigned)((lane & 7) * 16);
    const unsigned khalf = (unsigned)(16 * ((lane >> 3) & 1));
    unsigned bn[2];
    bn[0] = (unsigned)((nw + npL) * 128);
    bn[1] = (unsigned)((nw + 16 + npL) * 128);

    float acc[4][4][4];
    #pragma unroll
    for (int mt = 0; mt < 4; mt++)
        #pragma unroll
        for (int nt = 0; nt < 4; nt++)
            #pragma unroll
            for (int c = 0; c < 4; c++) acc[mt][nt][c] = 0.f;

    for (int kb = 0; kb < NCHUNK; kb++) {
        asm volatile("cp.async.wait_group 1;");   // fill(kb) drained (fill(kb+1) may pend)
        __syncthreads();
        if (kb + 2 < NCHUNK) cpB(kb + 2);          // stage (kb+2)%3: chunk kb-1's, done
        CP_COMMIT();                               // uniform 1 group per iter
        const unsigned Bst = Bbase + (unsigned)((kb % NBSTAGE) * BSTAGE);
        #pragma unroll
        for (int ksi = 0; ksi < 4; ksi++) {
            const unsigned kbyte = (unsigned)(2 * (kb * KC + ksi * 16));
            uint32_t afr[4][4];
            #pragma unroll
            for (int mt = 0; mt < 4; mt++)
                LDM4(afr[mt][0], afr[mt][1], afr[mt][2], afr[mt][3], aaddr[mt] + kbyte);
            uint32_t bfr[4][2];
            const unsigned koff = ((unsigned)(32 * ksi) + khalf) ^ swz;
            LDM4(bfr[0][0], bfr[0][1], bfr[1][0], bfr[1][1], Bst + bn[0] + koff);
            LDM4(bfr[2][0], bfr[2][1], bfr[3][0], bfr[3][1], Bst + bn[1] + koff);
            #pragma unroll
            for (int mt = 0; mt < 4; mt++)
                #pragma unroll
                for (int nt = 0; nt < 4; nt++)
                    MMA16816(acc[mt][nt], afr[mt], bfr[nt][0], bfr[nt][1]);
        }
    }

    // ---- epilogue: threshold gate -> candidate append ----
    const float T = g_thresh[b];
    const int g = lane >> 2, t4 = lane & 3;
    #pragma unroll
    for (int mt = 0; mt < 4; mt++)
        #pragma unroll
        for (int nt = 0; nt < 4; nt++)
            #pragma unroll
            for (int ci = 0; ci < 4; ci++) {
                float v = acc[mt][nt][ci];
                if (v > T) {
                    int time = t0 + mw + mt * 16 + g + 8 * (ci >> 1);
                    int atom = a0 + nw + nt * 8 + 2 * t4 + (ci & 1);
                    unsigned pos = atomicAdd(&g_cnt[b], 1u);
                    if (pos < CAP) g_cand_idx[b * CAP + pos] = ((unsigned)atom << 16) | (unsigned)time;
                }
            }
}

// ---------------- K3: exact fp32 re-score ----------------
__global__ void k3_rescore(const float* __restrict__ atoms) {
    int b = blockIdx.y;
    int warp = blockIdx.x * 8 + (threadIdx.x >> 5);
    int lane = threadIdx.x & 31;
    unsigned n = min(g_cnt[b], (unsigned)CAP);
    for (unsigned i = warp; i < n; i += 512) {
        unsigned pk = g_cand_idx[b * CAP + i];
        int atom = (int)(pk >> 16), t = (int)(pk & 0xFFFF);
        const float* op = g_origpad_f + (size_t)b * PADN + t;
        const float* ap = atoms + (size_t)atom * ATOM_SIZE;
        float s = 0.f;
        for (int k = lane; k < ATOM_SIZE; k += 32) s += op[k] * ap[k];
        #pragma unroll
        for (int o = 16; o; o >>= 1) s += __shfl_xor_sync(0xFFFFFFFFu, s, o);
        if (lane == 0) g_cand_score[b * CAP + i] = s;
    }
}

// ---------------- K4: exact top-64 (64 argmax rounds) ----------------
__global__ void k4_select() {
    int b = blockIdx.x;
    int tid = threadIdx.x;
    unsigned n = min(g_cnt[b], (unsigned)CAP);
    __shared__ float sv[256];
    __shared__ int   si[256];
    float* sc = g_cand_score + (size_t)b * CAP;
    for (int r = 0; r < K_SPARSE; r++) {
        float bv = -1e30f; int bi = -1;
        for (unsigned i = tid; i < n; i += 256) {
            float v = sc[i];
            if (v > bv) { bv = v; bi = (int)i; }
        }
        sv[tid] = bv; si[tid] = bi; __syncthreads();
        for (int st = 128; st; st >>= 1) {
            if (tid < st && sv[tid + st] > sv[tid]) { sv[tid] = sv[tid + st]; si[tid] = si[tid + st]; }
            __syncthreads();
        }
        if (tid == 0) {
            int i = si[0];
            unsigned pk = (i >= 0) ? g_cand_idx[b * CAP + i] : 0u;
            g_sel_val[b * K_SPARSE + r] = (i >= 0) ? sv[0] : 0.f;
            g_sel_at [b * K_SPARSE + r] = (int)(pk >> 16);
            g_sel_tm [b * K_SPARSE + r] = (int)(pk & 0xFFFF);
            if (i >= 0) sc[i] = -1e30f;
        }
        __syncthreads();
    }
}

// ---------------- K5: gather reconstruction ----------------
__global__ void k5_recon(const float* __restrict__ atoms, float* __restrict__ out) {
    int b = blockIdx.y;
    int t = blockIdx.x * 256 + threadIdx.x;
    __shared__ float v[K_SPARSE];
    __shared__ int   at[K_SPARSE], tmx[K_SPARSE];
    if (threadIdx.x < K_SPARSE) {
        v  [threadIdx.x] = g_sel_val[b * K_SPARSE + threadIdx.x];
        at [threadIdx.x] = g_sel_at [b * K_SPARSE + threadIdx.x];
        tmx[threadIdx.x] = g_sel_tm [b * K_SPARSE + threadIdx.x];
    }
    __syncthreads();
    float s = 0.f;
    for (int e = 0; e < K_SPARSE; e++) {
        int d = t - tmx[e];
        if ((unsigned)d < (unsigned)ATOM_SIZE) s += atoms[(size_t)at[e] * ATOM_SIZE + d] * v[e];
    }
    out[(size_t)b * N_SAMPLES + t] = s;
}

// ---------------- launch ----------------
extern "C" void kernel_launch(void* const* d_in, const int* in_sizes, int n_in,
                              void* d_out, int out_size) {
    const float* orig  = (const float*)d_in[0];   // [4,1,32768]
    const float* atoms = (const float*)d_in[1];   // [2048,1024]
    float* out = (float*)d_out;                   // [4,1,32768]

    cudaFuncSetAttribute(k2_score, cudaFuncAttributeMaxDynamicSharedMemorySize, SMEM_DYN);

    k_init<<<1, 32>>>();
    k0_stats<<<N_ATOMS + BATCH, 256>>>(orig, atoms);
    k0b_thresh<<<1, 32>>>();
    k1_convert<<<(N_ATOMS * ATOM_SIZE) / 256, 256>>>(orig, atoms);
    k2_score<<<dim3(N_SAMPLES / MT, N_ATOMS / NT, BATCH), 256, SMEM_DYN>>>();
    k3_rescore<<<dim3(64, BATCH), 256>>>(atoms);
    k4_select<<<BATCH, 256>>>();
    k5_recon<<<dim3(N_SAMPLES / 256, BATCH), 256>>>(atoms, out);
}